// round 15
// baseline (speedup 1.0000x reference)
#include <cuda_runtime.h>
#include <cuda_fp16.h>
#include <cstdint>
#include <math.h>

// ============================================================================
// R15: dtype-carrier-adaptive W8A16 GEMM.
// Theory: harness delivers fp16 tensors as float32 carriers, int8 as int32,
// and the fp16 output as a float32 buffer (stub lists only f32/i32/bf16).
// probe_r15 detects carriers at runtime (exact-fp16-roundtrip / int8-range
// tests); convert/dequant kernels build fp16 scratch with exact reference
// rounding; gemm = R13's HMMA (mma.sync.m16n8k16) pipeline, static 48KB smem;
// epilogue writes f32 or fp16 per detected output dtype.
// ============================================================================

#define M_TOTAL 8192
#define N_TOTAL 16384
#define K_TOTAL 4096

#define BM 256
#define BN 128
#define BK 32
#define K_ITERS (K_TOTAL / BK)   // 128
#define THREADS 512

#define A_STAGE_BYTES (BM * BK * 2)                 // 16384
#define B_STAGE_BYTES (BN * BK * 2)                 // 8192
#define STAGE_BYTES (A_STAGE_BYTES + B_STAGE_BYTES) // 24576
#define SMEM_TOTAL (2 * STAGE_BYTES)                // 49152 (48KB static)

#define NUM_MTILES (M_TOTAL / BM)  // 32
#define NUM_NTILES (N_TOTAL / BN)  // 128
#define GROUP_M 8

// ---------------------------------------------------------------------------
// device scratch: dtype flags, fp16 x, fp16 dequantized W
// flags: [0] x_is_f32 (also output_is_f32), [1] w_is_i32, [2] sc_is_f32,
//        [3] off_is_f32
// ---------------------------------------------------------------------------
__device__ int g_flags_r15[4];
__device__ __align__(1024) __half g_x_r15[(size_t)M_TOTAL * K_TOTAL];     // 64MB
__device__ __align__(1024) __half g_wdeq_r15[(size_t)N_TOTAL * K_TOTAL];  // 128MB

// ---------------------------------------------------------------------------
// helpers
// ---------------------------------------------------------------------------
__device__ __forceinline__ uint32_t smem_u32_r15(const void* p) {
    return (uint32_t)__cvta_generic_to_shared(p);
}
__device__ __forceinline__ void cp_async16_r15(uint32_t dst, const void* src) {
    asm volatile("cp.async.cg.shared.global [%0], [%1], 16;"
                 :: "r"(dst), "l"(src) : "memory");
}
#define CP_COMMIT() asm volatile("cp.async.commit_group;" ::: "memory")
#define CP_WAIT(n)  asm volatile("cp.async.wait_group %0;" :: "n"(n) : "memory")

__device__ __forceinline__ void ldsm_x4_r15(uint32_t& r0, uint32_t& r1, uint32_t& r2,
                                            uint32_t& r3, uint32_t addr) {
    asm volatile("ldmatrix.sync.aligned.m8n8.x4.shared.b16 {%0,%1,%2,%3}, [%4];"
                 : "=r"(r0), "=r"(r1), "=r"(r2), "=r"(r3) : "r"(addr));
}
__device__ __forceinline__ void ldsm_x2_r15(uint32_t& r0, uint32_t& r1, uint32_t addr) {
    asm volatile("ldmatrix.sync.aligned.m8n8.x2.shared.b16 {%0,%1}, [%2];"
                 : "=r"(r0), "=r"(r1) : "r"(addr));
}
__device__ __forceinline__ void mma_16816_r15(float* d, const uint32_t* a,
                                              const uint32_t* b) {
    asm volatile(
        "mma.sync.aligned.m16n8k16.row.col.f32.f16.f16.f32 "
        "{%0,%1,%2,%3}, {%4,%5,%6,%7}, {%8,%9}, {%0,%1,%2,%3};"
        : "+f"(d[0]), "+f"(d[1]), "+f"(d[2]), "+f"(d[3])
        : "r"(a[0]), "r"(a[1]), "r"(a[2]), "r"(a[3]), "r"(b[0]), "r"(b[1]));
}
__device__ __forceinline__ uint32_t sw64_r15(uint32_t off) {
    return off ^ ((off >> 3) & 0x30);
}

// ---------------------------------------------------------------------------
// Kernel 0: probe input carriers. Deterministic; safe (all reads in-bounds
// under BOTH carrier hypotheses). 256 threads x 16 samples each.
// ---------------------------------------------------------------------------
__global__ void __launch_bounds__(256) probe_r15(const void* x, const void* w,
                                                 const void* sc, const void* off) {
    __shared__ int votes[4];
    int tid = threadIdx.x;
    if (tid < 4) votes[tid] = 0;
    __syncthreads();
    int vx = 0, vw = 0, vs = 0, vo = 0;
#pragma unroll
    for (int t = 0; t < 16; t++) {
        uint32_t u = (uint32_t)(tid * 16 + t);
        // x: f32 read at idx < 2^23 (33MB) — in-bounds even if buffer is fp16 (67MB)
        uint32_t ix = (u * 2654435761u) & ((1u << 23) - 1);
        float xv = ((const float*)x)[ix];
        vx += (isfinite(xv) && xv == __half2float(__float2half_rn(xv))) ? 1 : 0;
        // w: i32 read at idx < 2^24 (67MB) — in-bounds even if buffer is int8 (67MB)
        uint32_t iw = (u * 2246822519u) & ((1u << 24) - 1);
        int wv = ((const int*)w)[iw];
        vw += (wv >= -128 && wv <= 127) ? 1 : 0;
        // scale/offset: 16384 elems; f32 read at idx < 4096 safe for fp16 buffer
        uint32_t is = (u * 3266489917u) & 4095u;
        float sv = ((const float*)sc)[is];
        vs += (isfinite(sv) && sv == __half2float(__float2half_rn(sv)) &&
               sv > 0.0f && sv < 0.25f) ? 1 : 0;
        float ov = ((const float*)off)[is];
        vo += (isfinite(ov) && ov == __half2float(__float2half_rn(ov)) &&
               fabsf(ov) < 32.0f) ? 1 : 0;
    }
    atomicAdd(&votes[0], vx);
    atomicAdd(&votes[1], vw);
    atomicAdd(&votes[2], vs);
    atomicAdd(&votes[3], vo);
    __syncthreads();
    if (tid == 0) {
#pragma unroll
        for (int k = 0; k < 4; k++) g_flags_r15[k] = (votes[k] >= 3072) ? 1 : 0;
    }
}

// ---------------------------------------------------------------------------
// Kernel 1: x carrier -> fp16 scratch (exact: promoted values roundtrip)
// ---------------------------------------------------------------------------
__global__ void __launch_bounds__(256) convert_x_r15(const void* x) {
    size_t i = (size_t)blockIdx.x * 256 + threadIdx.x;  // 8 elems per thread
    if (g_flags_r15[0]) {
        const float4* xf = (const float4*)x;
        float4 a = xf[2 * i], b = xf[2 * i + 1];
        __half2 h[4];
        h[0] = __floats2half2_rn(a.x, a.y);
        h[1] = __floats2half2_rn(a.z, a.w);
        h[2] = __floats2half2_rn(b.x, b.y);
        h[3] = __floats2half2_rn(b.z, b.w);
        ((uint4*)g_x_r15)[i] = *(const uint4*)h;
    } else {
        ((uint4*)g_x_r15)[i] = ((const uint4*)x)[i];
    }
}

// ---------------------------------------------------------------------------
// Kernel 2: dequant W -> fp16 scratch, exact reference rounding:
//   fp16( fp16( fp16(w) + off ) * scale )
// ---------------------------------------------------------------------------
__global__ void __launch_bounds__(256) dequant_w_r15(const void* w, const void* sc,
                                                     const void* off) {
    size_t i = (size_t)blockIdx.x * 256 + threadIdx.x;  // 8 elems per thread
    int row = (int)((i * 8) >> 12);                     // / K_TOTAL
    __half s = g_flags_r15[2] ? __float2half_rn(((const float*)sc)[row])
                              : ((const __half*)sc)[row];
    __half o = g_flags_r15[3] ? __float2half_rn(((const float*)off)[row])
                              : ((const __half*)off)[row];
    __half2 s2 = __half2half2(s), o2 = __half2half2(o);
    int v[8];
    if (g_flags_r15[1]) {
        int4 a = ((const int4*)w)[2 * i], b = ((const int4*)w)[2 * i + 1];
        v[0] = a.x; v[1] = a.y; v[2] = a.z; v[3] = a.w;
        v[4] = b.x; v[5] = b.y; v[6] = b.z; v[7] = b.w;
    } else {
        uint2 p = ((const uint2*)w)[i];
        uint32_t pk[2] = {p.x, p.y};
#pragma unroll
        for (int j = 0; j < 8; j++) v[j] = (int)(int8_t)(pk[j >> 2] >> ((j & 3) * 8));
    }
    __half2 r[4];
#pragma unroll
    for (int j = 0; j < 4; j++) {
        __half2 hv = __halves2half2(__int2half_rn(v[2 * j]), __int2half_rn(v[2 * j + 1]));
        r[j] = __hmul2(__hadd2(hv, o2), s2);
    }
    ((uint4*)g_wdeq_r15)[i] = *(const uint4*)r;
}

// ---------------------------------------------------------------------------
// Stage loader (R13 layout: 64B rows, SW64 swizzle)
// ---------------------------------------------------------------------------
__device__ __forceinline__ void load_stage_r15(uint32_t sbase, int pid_m, int pid_n,
                                               int tid, int ki, int buf) {
    const uint32_t sa = sbase + (uint32_t)buf * STAGE_BYTES;
    const uint32_t sbb = sa + A_STAGE_BYTES;
#pragma unroll
    for (int t = 0; t < 2; t++) {  // A: 256 rows x 4 segs
        int s = tid + t * 512;
        int row = s >> 2, seg = s & 3;
        uint32_t off = (uint32_t)(row * 64 + seg * 16);
        const __half* src =
            g_x_r15 + (size_t)(pid_m * BM + row) * K_TOTAL + ki * BK + seg * 8;
        cp_async16_r15(sa + sw64_r15(off), src);
    }
    {  // B: 128 rows x 4 segs
        int row = tid >> 2, seg = tid & 3;
        uint32_t off = (uint32_t)(row * 64 + seg * 16);
        const __half* src =
            g_wdeq_r15 + (size_t)(pid_n * BN + row) * K_TOTAL + ki * BK + seg * 8;
        cp_async16_r15(sbb + sw64_r15(off), src);
    }
}

// ---------------------------------------------------------------------------
// Kernel 3: HMMA GEMM (R13 compute), dtype-adaptive epilogue
// ---------------------------------------------------------------------------
__global__ void __launch_bounds__(THREADS, 1)
gemm_hmma_r15(void* out) {
    __shared__ __align__(128) unsigned char smem_raw[SMEM_TOTAL];
    const uint32_t sbase = smem_u32_r15(smem_raw);
    const int tid = threadIdx.x;
    const int wid = tid >> 5;
    const int lane = tid & 31;

    int pid = blockIdx.x;
    const int num_in_group = GROUP_M * NUM_NTILES;  // 1024
    int gid = pid / num_in_group;
    int pid_m = gid * GROUP_M + (pid % GROUP_M);
    int pid_n = (pid % num_in_group) / GROUP_M;

    const int wm = (wid >> 2) * 64;
    const int wn = (wid & 3) * 32;

    float d[4][4][4];
#pragma unroll
    for (int i = 0; i < 4; i++)
#pragma unroll
        for (int j = 0; j < 4; j++)
#pragma unroll
            for (int e = 0; e < 4; e++) d[i][j][e] = 0.0f;

    const uint32_t a_lane = (uint32_t)((lane & 15) * 64 + (lane >> 4) * 16);
    const uint32_t b_lane = (uint32_t)((lane & 7) * 64 + ((lane >> 3) & 1) * 16);

    load_stage_r15(sbase, pid_m, pid_n, tid, 0, 0);
    CP_COMMIT();

    for (int ki = 0; ki < K_ITERS; ki++) {
        const int cur = ki & 1;
        if (ki + 1 < K_ITERS) {
            load_stage_r15(sbase, pid_m, pid_n, tid, ki + 1, (ki + 1) & 1);
            CP_COMMIT();
            CP_WAIT(1);
        } else {
            CP_WAIT(0);
        }
        __syncthreads();

        const uint32_t sa = sbase + (uint32_t)cur * STAGE_BYTES;
        const uint32_t sbb = sa + A_STAGE_BYTES;

#pragma unroll
        for (int kk = 0; kk < 2; kk++) {
            const uint32_t kb = (uint32_t)(kk * 32);
            uint32_t a[4][4], b[4][2];
#pragma unroll
            for (int i = 0; i < 4; i++) {
                uint32_t off = (uint32_t)((wm + i * 16) * 64) + a_lane + kb;
                ldsm_x4_r15(a[i][0], a[i][1], a[i][2], a[i][3], sa + sw64_r15(off));
            }
#pragma unroll
            for (int j = 0; j < 4; j++) {
                uint32_t off = (uint32_t)((wn + j * 8) * 64) + b_lane + kb;
                ldsm_x2_r15(b[j][0], b[j][1], sbb + sw64_r15(off));
            }
#pragma unroll
            for (int i = 0; i < 4; i++)
#pragma unroll
                for (int j = 0; j < 4; j++) mma_16816_r15(d[i][j], a[i], b[j]);
        }
        __syncthreads();
    }

    // epilogue: round to fp16 (reference), store in detected output dtype
    const int out_f32 = g_flags_r15[0];
    const int row_in_warp = lane >> 2;
    const int col_in_warp = (lane & 3) * 2;
#pragma unroll
    for (int i = 0; i < 4; i++) {
#pragma unroll
        for (int j = 0; j < 4; j++) {
            int r0 = pid_m * BM + wm + i * 16 + row_in_warp;
            int c = pid_n * BN + wn + j * 8 + col_in_warp;
            __half2 lo = __floats2half2_rn(d[i][j][0], d[i][j][1]);
            __half2 hi = __floats2half2_rn(d[i][j][2], d[i][j][3]);
            if (out_f32) {
                float* of = (float*)out;
                *(float2*)(of + (size_t)r0 * N_TOTAL + c) =
                    make_float2(__half2float(lo.x), __half2float(lo.y));
                *(float2*)(of + (size_t)(r0 + 8) * N_TOTAL + c) =
                    make_float2(__half2float(hi.x), __half2float(hi.y));
            } else {
                __half* oh = (__half*)out;
                *(__half2*)(oh + (size_t)r0 * N_TOTAL + c) = lo;
                *(__half2*)(oh + (size_t)(r0 + 8) * N_TOTAL + c) = hi;
            }
        }
    }
}

// ---------------------------------------------------------------------------
// Host launch — plain launches only
// ---------------------------------------------------------------------------
extern "C" void kernel_launch(void* const* d_in, const int* in_sizes, int n_in,
                              void* d_out, int out_size) {
    const void* x = d_in[0];
    const void* w = d_in[1];
    const void* w_scale = d_in[2];
    const void* w_offset = d_in[3];

    probe_r15<<<1, 256>>>(x, w, w_scale, w_offset);

    {   // x: 33,554,432 elems / 8 per thread / 256 per block
        size_t n_vec = (size_t)M_TOTAL * K_TOTAL / 8;
        convert_x_r15<<<(unsigned)(n_vec / 256), 256>>>(x);
    }
    {   // w: 67,108,864 elems / 8 per thread
        size_t n_vec = (size_t)N_TOTAL * K_TOTAL / 8;
        dequant_w_r15<<<(unsigned)(n_vec / 256), 256>>>(w, w_scale, w_offset);
    }

    gemm_hmma_r15<<<NUM_MTILES * NUM_NTILES, THREADS>>>(d_out);
}

// round 17
// speedup vs baseline: 3.6241x; 3.6241x over previous
#include <cuda_runtime.h>
#include <cuda_fp16.h>
#include <cuda.h>
#include <cstdint>
#include <math.h>

// ============================================================================
// R16: carrier-adaptive front-end (R15) + tcgen05 TMA GEMM (R5 lineage).
//   probe  : detect f32/i32 carriers (harness delivers fp16->f32, int8->i32)
//   convert: x carrier -> fp16 scratch g_x
//   dequant: w carrier -> fp16 scratch g_wdeq, exact ref rounding
//   gemm   : tcgen05 cg1 SS f16 MMA, 256x256x64 tile, 3-stage TMA pipeline,
//            warp-specialized (4 epi / 1 tma / 1 mma), f32/f16-adaptive epilogue
// ============================================================================

#define M_TOTAL 8192
#define N_TOTAL 16384
#define K_TOTAL 4096

#define BM 256
#define BN 256
#define BK 64
#define K_ITERS (K_TOTAL / BK)   // 64
#define STAGES 3
#define THREADS 192

#define A_STAGE_BYTES (BM * BK * 2)
#define B_STAGE_BYTES (BN * BK * 2)
#define STAGE_BYTES (A_STAGE_BYTES + B_STAGE_BYTES)  // 65536
#define SMEM_CTRL 1024
#define SMEM_A_OFF(s) (SMEM_CTRL + (s) * STAGE_BYTES)
#define SMEM_B_OFF(s) (SMEM_A_OFF(s) + A_STAGE_BYTES)
#define SMEM_TOTAL (SMEM_CTRL + STAGES * STAGE_BYTES)  // 197632

#define OFF_TMEM 0
#define OFF_FULL(s) (64 + (s) * 16)
#define OFF_EMPTY(s) (72 + (s) * 16)
#define OFF_DONE 112

#define NUM_MTILES (M_TOTAL / BM)  // 32
#define NUM_NTILES (N_TOTAL / BN)  // 64
#define GROUP_M 8

// idesc kind::f16: dtype=F32 (1<<4), N=128 -> 16<<17, M=128 -> 8<<24
#define MMA_IDESC 0x08200010u

#if defined(__CUDA_ARCH_FEAT_SM103_ALL) || defined(__CUDA_ARCH_FEAT_SM100_ALL) || \
    defined(__CUDA_ARCH_FEAT_SM101_ALL)
#define HAS_TCGEN05 1
#else
#define HAS_TCGEN05 0
#endif

// ---------------------------------------------------------------------------
// device scratch
// flags: [0] x_is_f32 (== out_is_f32), [1] w_is_i32, [2] sc_is_f32, [3] off_is_f32
// ---------------------------------------------------------------------------
__device__ int g_flags_r16[4];
__device__ __align__(1024) __half g_x_r16[(size_t)M_TOTAL * K_TOTAL];
__device__ __align__(1024) __half g_wdeq_r16[(size_t)N_TOTAL * K_TOTAL];

// ---------------------------------------------------------------------------
// PTX helpers
// ---------------------------------------------------------------------------
__device__ __forceinline__ uint32_t smem_u32_r16(const void* p) {
    return (uint32_t)__cvta_generic_to_shared(p);
}

#define MBAR_INIT(addr, cnt) \
    asm volatile("mbarrier.init.shared.b64 [%0], %1;" :: "r"(addr), "r"(cnt) : "memory")

#define MBAR_EXPECT_TX(addr, bytes) \
    asm volatile("mbarrier.arrive.expect_tx.shared.b64 _, [%0], %1;" \
                 :: "r"(addr), "r"(bytes) : "memory")

#define MBAR_WAIT_PARITY(addr, parity) do {                                   \
    uint32_t _m = (addr); uint32_t _p = (parity); uint32_t _done;             \
    asm volatile("{\n\t.reg .pred p;\n\t"                                     \
        "mbarrier.try_wait.parity.acquire.cta.shared::cta.b64 p, [%1], %2;\n\t" \
        "selp.b32 %0, 1, 0, p;\n\t}"                                          \
        : "=r"(_done) : "r"(_m), "r"(_p) : "memory");                         \
    if (!_done) {                                                             \
        asm volatile("{\n\t.reg .pred P1;\n\t"                                \
            "WL_%=:\n\t"                                                      \
            "mbarrier.try_wait.parity.acquire.cta.shared::cta.b64 P1, [%0], %1, 0x989680;\n\t" \
            "@P1 bra.uni WD_%=;\n\t"                                          \
            "bra.uni WL_%=;\n\t"                                              \
            "WD_%=:\n\t}"                                                     \
            :: "r"(_m), "r"(_p) : "memory");                                  \
    }                                                                         \
} while (0)

#if HAS_TCGEN05

#define TC_ALLOC(slot_addr, ncols) \
    asm volatile("tcgen05.alloc.cta_group::1.sync.aligned.shared::cta.b32 [%0], %1;" \
                 :: "r"(slot_addr), "r"(ncols) : "memory")
#define TC_DEALLOC(tmem, ncols) \
    asm volatile("tcgen05.dealloc.cta_group::1.sync.aligned.b32 %0, %1;" \
                 :: "r"(tmem), "r"(ncols))
#define TC_COMMIT(mbar) \
    asm volatile("tcgen05.commit.cta_group::1.mbarrier::arrive::one.shared::cluster.b64 [%0];" \
                 :: "r"(mbar) : "memory")
#define TC_FENCE_AFTER() \
    asm volatile("tcgen05.fence::after_thread_sync;" ::: "memory")
#define TC_FENCE_BEFORE() \
    asm volatile("tcgen05.fence::before_thread_sync;" ::: "memory")
#define TC_WAIT_LD() \
    asm volatile("tcgen05.wait::ld.sync.aligned;" ::: "memory")

__device__ __forceinline__ void mma_f16_ss_r16(uint32_t d_tmem, uint64_t a_desc,
                                               uint64_t b_desc, uint32_t idesc,
                                               uint32_t accum) {
    asm volatile(
        "{\n\t.reg .pred p;\n\t"
        "setp.ne.u32 p, %5, 0;\n\t"
        "tcgen05.mma.cta_group::1.kind::f16 [%0], %1, %2, %3, {%4, %4, %4, %4}, p;\n\t}"
        :: "r"(d_tmem), "l"(a_desc), "l"(b_desc), "r"(idesc), "r"(0u), "r"(accum)
        : "memory");
}

#define TC_LD_X32(r, tmem) \
    asm volatile("tcgen05.ld.sync.aligned.32x32b.x32.b32 " \
        "{%0, %1, %2, %3, %4, %5, %6, %7, " \
        " %8, %9, %10, %11, %12, %13, %14, %15, " \
        " %16, %17, %18, %19, %20, %21, %22, %23, " \
        " %24, %25, %26, %27, %28, %29, %30, %31}, [%32];" \
        : "=r"((r)[0]),  "=r"((r)[1]),  "=r"((r)[2]),  "=r"((r)[3]), \
          "=r"((r)[4]),  "=r"((r)[5]),  "=r"((r)[6]),  "=r"((r)[7]), \
          "=r"((r)[8]),  "=r"((r)[9]),  "=r"((r)[10]), "=r"((r)[11]), \
          "=r"((r)[12]), "=r"((r)[13]), "=r"((r)[14]), "=r"((r)[15]), \
          "=r"((r)[16]), "=r"((r)[17]), "=r"((r)[18]), "=r"((r)[19]), \
          "=r"((r)[20]), "=r"((r)[21]), "=r"((r)[22]), "=r"((r)[23]), \
          "=r"((r)[24]), "=r"((r)[25]), "=r"((r)[26]), "=r"((r)[27]), \
          "=r"((r)[28]), "=r"((r)[29]), "=r"((r)[30]), "=r"((r)[31]) \
        : "r"(tmem))

#endif  // HAS_TCGEN05

__device__ __forceinline__ void tma_load_2d_r16(uint32_t smem_dst,
                                                const CUtensorMap* map, int32_t cx,
                                                int32_t cy, uint32_t mbar) {
    asm volatile(
        "cp.async.bulk.tensor.2d.shared::cta.global.tile.mbarrier::complete_tx::bytes "
        "[%0], [%1, {%2, %3}], [%4];"
        :: "r"(smem_dst), "l"(map), "r"(cx), "r"(cy), "r"(mbar)
        : "memory");
}

// SW128 K-major: layout=2, version=1, SBO=64, LBO=1 (== 0x4000404000010000)
static constexpr uint64_t SMEM_DESC_BASE_SW128 =
    (uint64_t(2) << 61) | (uint64_t(1) << 46) | (uint64_t(64) << 32) | (uint64_t(1) << 16);

__device__ __forceinline__ uint64_t make_desc_r16(uint32_t smem_addr) {
    return SMEM_DESC_BASE_SW128 | ((uint64_t)(smem_addr >> 4) & 0x3FFF);
}

// ---------------------------------------------------------------------------
// Kernel 0: probe input carriers (R15, proven)
// ---------------------------------------------------------------------------
__global__ void __launch_bounds__(256) probe_r16(const void* x, const void* w,
                                                 const void* sc, const void* off) {
    __shared__ int votes[4];
    int tid = threadIdx.x;
    if (tid < 4) votes[tid] = 0;
    __syncthreads();
    int vx = 0, vw = 0, vs = 0, vo = 0;
#pragma unroll
    for (int t = 0; t < 16; t++) {
        uint32_t u = (uint32_t)(tid * 16 + t);
        uint32_t ix = (u * 2654435761u) & ((1u << 23) - 1);
        float xv = ((const float*)x)[ix];
        vx += (isfinite(xv) && xv == __half2float(__float2half_rn(xv))) ? 1 : 0;
        uint32_t iw = (u * 2246822519u) & ((1u << 24) - 1);
        int wv = ((const int*)w)[iw];
        vw += (wv >= -128 && wv <= 127) ? 1 : 0;
        uint32_t is = (u * 3266489917u) & 4095u;
        float sv = ((const float*)sc)[is];
        vs += (isfinite(sv) && sv == __half2float(__float2half_rn(sv)) &&
               sv > 0.0f && sv < 0.25f) ? 1 : 0;
        float ov = ((const float*)off)[is];
        vo += (isfinite(ov) && ov == __half2float(__float2half_rn(ov)) &&
               fabsf(ov) < 32.0f) ? 1 : 0;
    }
    atomicAdd(&votes[0], vx);
    atomicAdd(&votes[1], vw);
    atomicAdd(&votes[2], vs);
    atomicAdd(&votes[3], vo);
    __syncthreads();
    if (tid == 0) {
#pragma unroll
        for (int k = 0; k < 4; k++) g_flags_r16[k] = (votes[k] >= 3072) ? 1 : 0;
    }
}

// ---------------------------------------------------------------------------
// Kernel 1: x carrier -> fp16 scratch
// ---------------------------------------------------------------------------
__global__ void __launch_bounds__(256) convert_x_r16(const void* x) {
    size_t i = (size_t)blockIdx.x * 256 + threadIdx.x;
    if (g_flags_r16[0]) {
        const float4* xf = (const float4*)x;
        float4 a = xf[2 * i], b = xf[2 * i + 1];
        __half2 h[4];
        h[0] = __floats2half2_rn(a.x, a.y);
        h[1] = __floats2half2_rn(a.z, a.w);
        h[2] = __floats2half2_rn(b.x, b.y);
        h[3] = __floats2half2_rn(b.z, b.w);
        ((uint4*)g_x_r16)[i] = *(const uint4*)h;
    } else {
        ((uint4*)g_x_r16)[i] = ((const uint4*)x)[i];
    }
}

// ---------------------------------------------------------------------------
// Kernel 2: dequant W -> fp16 scratch, exact reference rounding
// ---------------------------------------------------------------------------
__global__ void __launch_bounds__(256) dequant_w_r16(const void* w, const void* sc,
                                                     const void* off) {
    size_t i = (size_t)blockIdx.x * 256 + threadIdx.x;
    int row = (int)((i * 8) >> 12);
    __half s = g_flags_r16[2] ? __float2half_rn(((const float*)sc)[row])
                              : ((const __half*)sc)[row];
    __half o = g_flags_r16[3] ? __float2half_rn(((const float*)off)[row])
                              : ((const __half*)off)[row];
    __half2 s2 = __half2half2(s), o2 = __half2half2(o);
    int v[8];
    if (g_flags_r16[1]) {
        int4 a = ((const int4*)w)[2 * i], b = ((const int4*)w)[2 * i + 1];
        v[0] = a.x; v[1] = a.y; v[2] = a.z; v[3] = a.w;
        v[4] = b.x; v[5] = b.y; v[6] = b.z; v[7] = b.w;
    } else {
        uint2 p = ((const uint2*)w)[i];
        uint32_t pk[2] = {p.x, p.y};
#pragma unroll
        for (int j = 0; j < 8; j++) v[j] = (int)(int8_t)(pk[j >> 2] >> ((j & 3) * 8));
    }
    __half2 r[4];
#pragma unroll
    for (int j = 0; j < 4; j++) {
        __half2 hv = __halves2half2(__int2half_rn(v[2 * j]), __int2half_rn(v[2 * j + 1]));
        r[j] = __hmul2(__hadd2(hv, o2), s2);
    }
    ((uint4*)g_wdeq_r16)[i] = *(const uint4*)r;
}

// ---------------------------------------------------------------------------
// Kernel 3: tcgen05 GEMM (R5 lineage), dtype-adaptive epilogue
// ---------------------------------------------------------------------------
__global__ void __launch_bounds__(THREADS, 1) __cluster_dims__(1, 1, 1)
gemm_tc_r16(const __grid_constant__ CUtensorMap tma_a,
            const __grid_constant__ CUtensorMap tma_b,
            void* __restrict__ out) {
    int pid = blockIdx.x;
    const int num_in_group = GROUP_M * NUM_NTILES;  // 512
    int gid = pid / num_in_group;
    int pid_m = gid * GROUP_M + (pid % GROUP_M);
    int pid_n = (pid % num_in_group) / GROUP_M;

#if HAS_TCGEN05
    extern __shared__ char smem[];
    const uint32_t sb = smem_u32_r16(smem);
    const int tid = threadIdx.x;
    const int wid = tid >> 5;
    const int lane = tid & 31;

    if (tid == 0) {
#pragma unroll
        for (int s = 0; s < STAGES; s++) {
            MBAR_INIT(sb + OFF_FULL(s), 1);
            MBAR_INIT(sb + OFF_EMPTY(s), 1);
        }
        MBAR_INIT(sb + OFF_DONE, 1);
    }
    if (wid == 5) {
        TC_ALLOC(sb + OFF_TMEM, 512);
    }
    __syncthreads();

    uint32_t tmem_base;
    asm volatile("ld.shared.b32 %0, [%1];" : "=r"(tmem_base) : "r"(sb + OFF_TMEM));

    if (wid == 4) {
        // ---------------- TMA producer ----------------
        if (lane == 0) {
            int phase = 1;
            for (int ki = 0; ki < K_ITERS; ki++) {
                int s = ki % STAGES;
                if (s == 0 && ki != 0) phase ^= 1;
                MBAR_WAIT_PARITY(sb + OFF_EMPTY(s), phase);
                MBAR_EXPECT_TX(sb + OFF_FULL(s), STAGE_BYTES);
                tma_load_2d_r16(sb + SMEM_A_OFF(s), &tma_a, ki * BK, pid_m * BM,
                                sb + OFF_FULL(s));
                tma_load_2d_r16(sb + SMEM_B_OFF(s), &tma_b, ki * BK, pid_n * BN,
                                sb + OFF_FULL(s));
            }
        }
    } else if (wid == 5) {
        // ---------------- MMA warp ----------------
        if (lane == 0) {
            int phase = 0;
            for (int ki = 0; ki < K_ITERS; ki++) {
                int s = ki % STAGES;
                if (s == 0 && ki != 0) phase ^= 1;
                MBAR_WAIT_PARITY(sb + OFF_FULL(s), phase);
                uint64_t a_desc = make_desc_r16(sb + SMEM_A_OFF(s));
                uint64_t b_desc = make_desc_r16(sb + SMEM_B_OFF(s));
#pragma unroll
                for (int h = 0; h < 2; h++) {
#pragma unroll
                    for (int nh = 0; nh < 2; nh++) {
#pragma unroll
                        for (int ks = 0; ks < 4; ks++) {
                            mma_f16_ss_r16(tmem_base + h * 256 + nh * 128,
                                           a_desc + (uint64_t)h * 1024 + ks * 2,
                                           b_desc + (uint64_t)nh * 1024 + ks * 2,
                                           MMA_IDESC,
                                           (ki == 0 && ks == 0) ? 0u : 1u);
                        }
                    }
                }
                TC_COMMIT(sb + OFF_EMPTY(s));
            }
            TC_COMMIT(sb + OFF_DONE);
        }
    }

    // ---------------- epilogue warps 0..3 ----------------
    if (wid < 4) {
        MBAR_WAIT_PARITY(sb + OFF_DONE, 0);
        TC_FENCE_AFTER();
        const int out_f32 = g_flags_r16[0];
#pragma unroll
        for (int h = 0; h < 2; h++) {
            int mrow = pid_m * BM + h * 128 + wid * 32 + lane;
#pragma unroll
            for (int cb = 0; cb < 8; cb++) {
                uint32_t r[32];
                TC_LD_X32(r, tmem_base + h * 256 + cb * 32);
                TC_WAIT_LD();
                if (out_f32) {
                    // round to fp16 (reference), store promoted f32
                    float vals[32];
#pragma unroll
                    for (int j = 0; j < 32; j++) {
                        vals[j] = __half2float(__float2half_rn(__uint_as_float(r[j])));
                    }
                    float* orow =
                        (float*)out + (size_t)mrow * N_TOTAL + pid_n * BN + cb * 32;
#pragma unroll
                    for (int j = 0; j < 8; j++) {
                        ((float4*)orow)[j] = ((const float4*)vals)[j];
                    }
                } else {
                    __half2 hh[16];
#pragma unroll
                    for (int j = 0; j < 16; j++) {
                        hh[j] = __floats2half2_rn(__uint_as_float(r[2 * j]),
                                                  __uint_as_float(r[2 * j + 1]));
                    }
                    __half* orow =
                        (__half*)out + (size_t)mrow * N_TOTAL + pid_n * BN + cb * 32;
#pragma unroll
                    for (int j = 0; j < 4; j++) {
                        ((uint4*)orow)[j] = ((const uint4*)hh)[j];
                    }
                }
            }
        }
        TC_FENCE_BEFORE();
    }

    __syncthreads();
    if (wid == 5) {
        TC_DEALLOC(tmem_base, 512);
    }
#else
    // -------- fallback (never selected on sm_103a device) --------
    for (int idx = threadIdx.x; idx < BM * BN; idx += THREADS) {
        int m = pid_m * BM + idx / BN;
        int n = pid_n * BN + idx % BN;
        const __half2* xr = (const __half2*)(g_x_r16 + (size_t)m * K_TOTAL);
        const __half2* wr = (const __half2*)(g_wdeq_r16 + (size_t)n * K_TOTAL);
        float acc = 0.0f;
        for (int k = 0; k < K_TOTAL / 2; k++) {
            float2 a = __half22float2(xr[k]);
            float2 b = __half22float2(wr[k]);
            acc += a.x * b.x + a.y * b.y;
        }
        __half hv = __float2half_rn(acc);
        if (g_flags_r16[0])
            ((float*)out)[(size_t)m * N_TOTAL + n] = __half2float(hv);
        else
            ((__half*)out)[(size_t)m * N_TOTAL + n] = hv;
    }
#endif
}

// ---------------------------------------------------------------------------
// Host launch
// ---------------------------------------------------------------------------
typedef CUresult (*PFN_encodeTiled_r16)(
    CUtensorMap*, CUtensorMapDataType, cuuint32_t, void*,
    const cuuint64_t*, const cuuint64_t*, const cuuint32_t*, const cuuint32_t*,
    CUtensorMapInterleave, CUtensorMapSwizzle, CUtensorMapL2promotion,
    CUtensorMapFloatOOBfill);

static PFN_encodeTiled_r16 get_encode_fn_r16() {
    static PFN_encodeTiled_r16 fn = nullptr;
    if (!fn) {
        void* p = nullptr;
        cudaDriverEntryPointQueryResult st;
        cudaGetDriverEntryPointByVersion("cuTensorMapEncodeTiled", &p, 12000,
                                         cudaEnableDefault, &st);
        fn = (PFN_encodeTiled_r16)p;
    }
    return fn;
}

static void make_map_r16(CUtensorMap* map, void* base, uint64_t rows, uint64_t cols,
                         uint32_t box_cols, uint32_t box_rows) {
    cuuint64_t dims[2] = {cols, rows};
    cuuint64_t strides[1] = {cols * 2};
    cuuint32_t box[2] = {box_cols, box_rows};
    cuuint32_t estr[2] = {1, 1};
    get_encode_fn_r16()(map, CU_TENSOR_MAP_DATA_TYPE_FLOAT16, 2, base, dims, strides,
                        box, estr, CU_TENSOR_MAP_INTERLEAVE_NONE,
                        CU_TENSOR_MAP_SWIZZLE_128B, CU_TENSOR_MAP_L2_PROMOTION_L2_128B,
                        CU_TENSOR_MAP_FLOAT_OOB_FILL_NONE);
}

extern "C" void kernel_launch(void* const* d_in, const int* in_sizes, int n_in,
                              void* d_out, int out_size) {
    const void* x = d_in[0];
    const void* w = d_in[1];
    const void* w_scale = d_in[2];
    const void* w_offset = d_in[3];

    probe_r16<<<1, 256>>>(x, w, w_scale, w_offset);
    {
        size_t n_vec = (size_t)M_TOTAL * K_TOTAL / 8;
        convert_x_r16<<<(unsigned)(n_vec / 256), 256>>>(x);
    }
    {
        size_t n_vec = (size_t)N_TOTAL * K_TOTAL / 8;
        dequant_w_r16<<<(unsigned)(n_vec / 256), 256>>>(w, w_scale, w_offset);
    }

    void* xp = nullptr;
    void* wp = nullptr;
    cudaGetSymbolAddress(&xp, g_x_r16);
    cudaGetSymbolAddress(&wp, g_wdeq_r16);

    CUtensorMap tma_a, tma_b;
    make_map_r16(&tma_a, xp, M_TOTAL, K_TOTAL, BK, BM);
    make_map_r16(&tma_b, wp, N_TOTAL, K_TOTAL, BK, BN);

    cudaFuncSetAttribute(gemm_tc_r16, cudaFuncAttributeMaxDynamicSharedMemorySize,
                         SMEM_TOTAL);
    gemm_tc_r16<<<NUM_MTILES * NUM_NTILES, THREADS, SMEM_TOTAL>>>(tma_a, tma_b, d_out);
}